// round 3
// baseline (speedup 1.0000x reference)
#include <cuda_runtime.h>
#include <math.h>

// Problem dims
constexpr int kB = 512;   // batch
constexpr int kS = 168;   // encoder seq len
constexpr int kI = 8;     // input features
constexpr int kH = 512;   // hidden
constexpr int kF = 256;   // fc1 width
constexpr int kP = 24;    // decoder steps
constexpr int kG = 4 * kH; // 2048 gates

// ---------------- scratch (device globals; no allocations allowed) ----------
__device__ float g_y0[(size_t)kS * kB * 2 * kH];   // BiLSTM L0 output concat [s][b][1024]
__device__ float g_G1[(size_t)2 * kS * kB * kG];   // precomputed L1 input projections [d][s][b][2048]
__device__ float g_h[8][kB * kH];                  // 4 encoder runs x ping-pong
__device__ float g_c[4][kB * kH];                  // 4 encoder runs (in-place)
__device__ float g_dh[4][kB * kH];                 // decoder: 2 cells x ping-pong
__device__ float g_dc[2][kB * kH];
__device__ float g_din[kB * kI];                   // decoder input vector
__device__ float g_z[kB * kF];                     // fc1 activations

// ---------------- shared tile layout ----------------------------------------
struct SmemT {
    float As[16][64];     // A tile: As[k][row]
    float Bs[128][17];    // B tile: Bs[j_local][k], padded stride 17 (conflict-free)
};

// Tiled GEMM accumulate: block computes 64 rows x 128 weight-rows, K loop.
// Weight-row mapping: j_global = (j_local/32)*gstride + ubase + (j_local%32).
// For LSTM gates: gstride=512 -> thread (u = tid&31) owns gates i,f,g,o of unit ubase+u.
// For plain GEMM: gstride=32 -> j_global = ubase + j_local (contiguous 128 cols).
__device__ __forceinline__ void gemm_acc(
    float acc[4][8],
    const float* __restrict__ A, int lda,
    const float* __restrict__ Bm, int ldb,
    int K, int gstride, int ubase,
    SmemT& sm)
{
    const int tid = threadIdx.x;
    const int u = tid & 31, rg = tid >> 5;
    const int lrow = tid >> 2;
    const int lk4 = (tid & 3) * 4;
    for (int k0 = 0; k0 < K; k0 += 16) {
        __syncthreads();
        {
            float4 v = *reinterpret_cast<const float4*>(A + (size_t)lrow * lda + k0 + lk4);
            sm.As[lk4 + 0][lrow] = v.x;
            sm.As[lk4 + 1][lrow] = v.y;
            sm.As[lk4 + 2][lrow] = v.z;
            sm.As[lk4 + 3][lrow] = v.w;
        }
#pragma unroll
        for (int pass = 0; pass < 2; ++pass) {
            int jl = lrow + pass * 64;
            int jg = (jl >> 5) * gstride + ubase + (jl & 31);
            float4 v = *reinterpret_cast<const float4*>(Bm + (size_t)jg * ldb + k0 + lk4);
            sm.Bs[jl][lk4 + 0] = v.x;
            sm.Bs[jl][lk4 + 1] = v.y;
            sm.Bs[jl][lk4 + 2] = v.z;
            sm.Bs[jl][lk4 + 3] = v.w;
        }
        __syncthreads();
#pragma unroll
        for (int kk = 0; kk < 16; ++kk) {
            float4 a0 = *reinterpret_cast<const float4*>(&sm.As[kk][rg * 8]);
            float4 a1 = *reinterpret_cast<const float4*>(&sm.As[kk][rg * 8 + 4]);
            float b0 = sm.Bs[u][kk];
            float b1 = sm.Bs[32 + u][kk];
            float b2 = sm.Bs[64 + u][kk];
            float b3 = sm.Bs[96 + u][kk];
            float a[8] = {a0.x, a0.y, a0.z, a0.w, a1.x, a1.y, a1.z, a1.w};
#pragma unroll
            for (int i = 0; i < 8; ++i) {
                acc[0][i] += b0 * a[i];
                acc[1][i] += b1 * a[i];
                acc[2][i] += b2 * a[i];
                acc[3][i] += b3 * a[i];
            }
        }
    }
}

// Small-K (K=8) input projection accumulate (x @ Wih.T), reuses smem.
__device__ __forceinline__ void smallk_acc(
    float acc[4][8],
    const float* __restrict__ xA, int ldx,
    const float* __restrict__ W, // [2048][8]
    int gstride, int ubase, SmemT& sm)
{
    const int tid = threadIdx.x;
    float* xs = &sm.As[0][0];   // 64*8
    float* ws = &sm.Bs[0][0];   // 128*8
    __syncthreads();
    for (int i = tid; i < 64 * 8; i += 256)
        xs[i] = xA[(size_t)(i >> 3) * ldx + (i & 7)];
    for (int i = tid; i < 128 * 8; i += 256) {
        int jl = i >> 3;
        int jg = (jl >> 5) * gstride + ubase + (jl & 31);
        ws[i] = W[(size_t)jg * 8 + (i & 7)];
    }
    __syncthreads();
    const int u = tid & 31, rg = tid >> 5;
#pragma unroll
    for (int k = 0; k < 8; ++k) {
        float b0 = ws[(u) * 8 + k];
        float b1 = ws[(32 + u) * 8 + k];
        float b2 = ws[(64 + u) * 8 + k];
        float b3 = ws[(96 + u) * 8 + k];
#pragma unroll
        for (int i = 0; i < 8; ++i) {
            float a = xs[(rg * 8 + i) * 8 + k];
            acc[0][i] += b0 * a;
            acc[1][i] += b1 * a;
            acc[2][i] += b2 * a;
            acc[3][i] += b3 * a;
        }
    }
}

__device__ __forceinline__ float sigf(float v) { return 1.f / (1.f + expf(-v)); }

// Fused LSTM pointwise epilogue. All pointers pre-offset to the block row r0.
__device__ __forceinline__ void lstm_epilogue(
    float acc[4][8],
    const float* __restrict__ gbase,   // optional precomputed gates [row][2048] (incl bias)
    const float* __restrict__ bias,    // optional [2048]
    float* __restrict__ c,             // [row][512]
    float* __restrict__ hout,          // [row][512]
    float* __restrict__ yout, int ystride,  // optional
    int ubase)
{
    const int tid = threadIdx.x;
    const int u = tid & 31, rg = tid >> 5;
    const int ug = ubase + u;
    float b0 = 0.f, b1 = 0.f, b2 = 0.f, b3 = 0.f;
    if (bias) { b0 = bias[ug]; b1 = bias[512 + ug]; b2 = bias[1024 + ug]; b3 = bias[1536 + ug]; }
#pragma unroll
    for (int i = 0; i < 8; ++i) {
        int row = rg * 8 + i;
        float gi = acc[0][i] + b0;
        float gf = acc[1][i] + b1;
        float gg = acc[2][i] + b2;
        float go = acc[3][i] + b3;
        if (gbase) {
            const float* gb = gbase + (size_t)row * kG;
            gi += gb[ug]; gf += gb[512 + ug]; gg += gb[1024 + ug]; go += gb[1536 + ug];
        }
        gi = sigf(gi); gf = sigf(gf); gg = tanhf(gg); go = sigf(go);
        size_t idx = (size_t)row * kH + ug;
        float cv = gf * c[idx] + gi * gg;
        c[idx] = cv;
        float hv = go * tanhf(cv);
        hout[idx] = hv;
        if (yout) yout[(size_t)row * ystride + ug] = hv;
    }
}

// ---------------- kernels ----------------------------------------------------

__global__ void init_k()
{
    size_t i = (size_t)blockIdx.x * blockDim.x + threadIdx.x;
    size_t stride = (size_t)gridDim.x * blockDim.x;
    for (size_t j = i; j < (size_t)8 * kB * kH; j += stride) (&g_h[0][0])[j] = 0.f;
    for (size_t j = i; j < (size_t)4 * kB * kH; j += stride) (&g_c[0][0])[j] = 0.f;
}

// Encoder layer 0 step: both directions (blockIdx.z). Fuses x-projection (K=8).
__global__ __launch_bounds__(256) void enc_l0_step_k(
    const float* __restrict__ x, const float* __restrict__ Wih,
    const float* __restrict__ Whh, const float* __restrict__ bias,
    int t, int ping)
{
    __shared__ SmemT sm;
    int d = blockIdx.z;
    int s = d ? (kS - 1 - t) : t;
    int r0 = blockIdx.x * 64;
    int ubase = blockIdx.y * 32;
    float acc[4][8] = {};
    gemm_acc(acc, g_h[d * 2 + ping] + (size_t)r0 * kH, kH,
             Whh + (size_t)d * kG * kH, kH, kH, kH, ubase, sm);
    smallk_acc(acc, x + (size_t)r0 * (kS * kI) + (size_t)s * kI, kS * kI,
               Wih + (size_t)d * kG * kI, kH, ubase, sm);
    lstm_epilogue(acc, nullptr, bias + d * kG,
                  g_c[d] + (size_t)r0 * kH,
                  g_h[d * 2 + (ping ^ 1)] + (size_t)r0 * kH,
                  g_y0 + (size_t)s * kB * (2 * kH) + (size_t)r0 * (2 * kH) + (size_t)d * kH,
                  2 * kH, ubase);
}

// Batched L1 input projection: G1[d][s][b][:] = y0[s][b][:] @ Wih1[d].T + b1[d]
__global__ __launch_bounds__(256) void g1_gemm_k(
    const float* __restrict__ Wih1, const float* __restrict__ b1)
{
    __shared__ SmemT sm;
    int d = blockIdx.z;
    size_t m0 = (size_t)blockIdx.x * 64;
    int j0 = blockIdx.y * 128;
    float acc[4][8] = {};
    gemm_acc(acc, g_y0 + m0 * (2 * kH), 2 * kH,
             Wih1 + (size_t)d * kG * (2 * kH), 2 * kH, 2 * kH, 32, j0, sm);
    const int tid = threadIdx.x;
    const int u = tid & 31, rg = tid >> 5;
    float* C = g_G1 + (size_t)d * kS * kB * kG;
#pragma unroll
    for (int g = 0; g < 4; ++g) {
        int j = j0 + g * 32 + u;
        float bb = b1[d * kG + j];
#pragma unroll
        for (int i = 0; i < 8; ++i) {
            size_t m = m0 + rg * 8 + i;
            C[m * kG + j] = acc[g][i] + bb;
        }
    }
}

// Encoder layer 1 step: gates = G1[d][s] + h @ Whh1[d].T
__global__ __launch_bounds__(256) void enc_l1_step_k(
    const float* __restrict__ Whh1, int t, int ping)
{
    __shared__ SmemT sm;
    int d = blockIdx.z;
    int s = d ? (kS - 1 - t) : t;
    int r0 = blockIdx.x * 64;
    int ubase = blockIdx.y * 32;
    int run = 2 + d;
    float acc[4][8] = {};
    gemm_acc(acc, g_h[run * 2 + ping] + (size_t)r0 * kH, kH,
             Whh1 + (size_t)d * kG * kH, kH, kH, kH, ubase, sm);
    const float* gb = g_G1 + ((size_t)d * kS + s) * kB * kG + (size_t)r0 * kG;
    lstm_epilogue(acc, gb, nullptr,
                  g_c[2 + d] + (size_t)r0 * kH,
                  g_h[run * 2 + (ping ^ 1)] + (size_t)r0 * kH,
                  nullptr, 0, ubase);
}

// Sum fwd/bwd final states -> decoder init; grab last x timestep as dec input.
__global__ void combine_k(const float* __restrict__ x)
{
    int i = blockIdx.x * blockDim.x + threadIdx.x;
    if (i < kB * kH) {
        g_dh[0][i] = g_h[0][i] + g_h[2][i];
        g_dc[0][i] = g_c[0][i] + g_c[1][i];
        g_dh[2][i] = g_h[4][i] + g_h[6][i];
        g_dc[1][i] = g_c[2][i] + g_c[3][i];
    }
    if (i < kB * kI)
        g_din[i] = x[(size_t)(i >> 3) * (kS * kI) + (size_t)(kS - 1) * kI + (i & 7)];
}

__global__ __launch_bounds__(256) void dec_cell0_k(
    const float* __restrict__ Wih, const float* __restrict__ Whh,
    const float* __restrict__ bias, int ping)
{
    __shared__ SmemT sm;
    int r0 = blockIdx.x * 64;
    int ubase = blockIdx.y * 32;
    float acc[4][8] = {};
    gemm_acc(acc, g_dh[ping] + (size_t)r0 * kH, kH, Whh, kH, kH, kH, ubase, sm);
    smallk_acc(acc, g_din + (size_t)r0 * kI, kI, Wih, kH, ubase, sm);
    lstm_epilogue(acc, nullptr, bias,
                  g_dc[0] + (size_t)r0 * kH,
                  g_dh[ping ^ 1] + (size_t)r0 * kH, nullptr, 0, ubase);
}

__global__ __launch_bounds__(256) void dec_cell1_k(
    const float* __restrict__ Wih, const float* __restrict__ Whh,
    const float* __restrict__ bias, int p0new, int ping)
{
    __shared__ SmemT sm;
    int r0 = blockIdx.x * 64;
    int ubase = blockIdx.y * 32;
    float acc[4][8] = {};
    gemm_acc(acc, g_dh[2 + ping] + (size_t)r0 * kH, kH, Whh, kH, kH, kH, ubase, sm);
    gemm_acc(acc, g_dh[p0new] + (size_t)r0 * kH, kH, Wih, kH, kH, kH, ubase, sm);
    lstm_epilogue(acc, nullptr, bias,
                  g_dc[1] + (size_t)r0 * kH,
                  g_dh[2 + (ping ^ 1)] + (size_t)r0 * kH, nullptr, 0, ubase);
}

// z = relu(h1 @ fc1W.T + fc1b) ; tile 64 rows x 64 cols
__global__ __launch_bounds__(256) void fc1_k(
    const float* __restrict__ W, const float* __restrict__ b, int p1new)
{
    __shared__ float Hs[16][64];
    __shared__ float Ws[64][17];
    int r0 = blockIdx.x * 64;
    int j0 = blockIdx.y * 64;
    int tid = threadIdx.x;
    const float* h1 = g_dh[2 + p1new] + (size_t)r0 * kH;
    int j = tid & 63, rgrp = tid >> 6;
    float acc[16] = {};
    int lrow = tid >> 2, lk4 = (tid & 3) * 4;
    for (int k0 = 0; k0 < kH; k0 += 16) {
        __syncthreads();
        {
            float4 v = *reinterpret_cast<const float4*>(h1 + (size_t)lrow * kH + k0 + lk4);
            Hs[lk4 + 0][lrow] = v.x; Hs[lk4 + 1][lrow] = v.y;
            Hs[lk4 + 2][lrow] = v.z; Hs[lk4 + 3][lrow] = v.w;
        }
        {
            float4 v = *reinterpret_cast<const float4*>(W + (size_t)(j0 + lrow) * kH + k0 + lk4);
            Ws[lrow][lk4 + 0] = v.x; Ws[lrow][lk4 + 1] = v.y;
            Ws[lrow][lk4 + 2] = v.z; Ws[lrow][lk4 + 3] = v.w;
        }
        __syncthreads();
#pragma unroll
        for (int kk = 0; kk < 16; ++kk) {
            float w = Ws[j][kk];
#pragma unroll
            for (int r = 0; r < 16; ++r)
                acc[r] += Hs[kk][rgrp * 16 + r] * w;
        }
    }
    float bb = b[j0 + j];
#pragma unroll
    for (int r = 0; r < 16; ++r) {
        float v = acc[r] + bb;
        g_z[(size_t)(r0 + rgrp * 16 + r) * kF + j0 + j] = v > 0.f ? v : 0.f;
    }
}

// pred = z @ fc2W.T + fc2b ; write output column p; build next decoder input.
__global__ void fc2_k(
    const float* __restrict__ W2, const float* __restrict__ b2,
    const float* __restrict__ tf, float* __restrict__ out, int p)
{
    int w = threadIdx.x >> 5, lane = threadIdx.x & 31;
    int row = blockIdx.x * 8 + w;
    const float* z = g_z + (size_t)row * kF;
    float s = 0.f;
    for (int k = lane; k < kF; k += 32) s += z[k] * W2[k];
#pragma unroll
    for (int o = 16; o; o >>= 1) s += __shfl_xor_sync(0xffffffffu, s, o);
    if (lane == 0) {
        float pred = s + b2[0];
        out[row * kP + p] = pred;
        g_din[row * kI] = pred;  // next input feature 0
    }
    if (lane >= 1 && lane < 8)
        g_din[row * kI + lane] = tf[(size_t)row * (kP * kI) + (size_t)p * kI + lane];
}

// ---------------- host driver ------------------------------------------------
extern "C" void kernel_launch(void* const* d_in, const int* in_sizes, int n_in,
                              void* d_out, int out_size)
{
    (void)in_sizes; (void)n_in; (void)out_size;
    const float* x     = (const float*)d_in[0];
    const float* tf    = (const float*)d_in[1];
    const float* eWih0 = (const float*)d_in[2];
    const float* eWhh0 = (const float*)d_in[3];
    const float* eb0   = (const float*)d_in[4];
    const float* eWih1 = (const float*)d_in[5];
    const float* eWhh1 = (const float*)d_in[6];
    const float* eb1   = (const float*)d_in[7];
    const float* dWih0 = (const float*)d_in[8];
    const float* dWhh0 = (const float*)d_in[9];
    const float* db0   = (const float*)d_in[10];
    const float* dWih1 = (const float*)d_in[11];
    const float* dWhh1 = (const float*)d_in[12];
    const float* db1   = (const float*)d_in[13];
    const float* fc1W  = (const float*)d_in[14];
    const float* fc1b  = (const float*)d_in[15];
    const float* fc2W  = (const float*)d_in[16];
    const float* fc2b  = (const float*)d_in[17];
    float* out = (float*)d_out;

    init_k<<<512, 256>>>();

    // Encoder layer 0 (both directions per launch), fused x-projection.
    for (int t = 0; t < kS; ++t)
        enc_l0_step_k<<<dim3(8, 16, 2), 256>>>(x, eWih0, eWhh0, eb0, t, t & 1);

    // Batched layer-1 input projection (off the sequential chain).
    g1_gemm_k<<<dim3((kS * kB) / 64, kG / 128, 2), 256>>>(eWih1, eb1);

    // Encoder layer 1 recurrent chain (K=512 only).
    for (int t = 0; t < kS; ++t)
        enc_l1_step_k<<<dim3(8, 16, 2), 256>>>(eWhh1, t, t & 1);

    combine_k<<<1024, 256>>>(x);

    int p0 = 0, p1 = 0;
    for (int p = 0; p < kP; ++p) {
        dec_cell0_k<<<dim3(8, 16, 1), 256>>>(dWih0, dWhh0, db0, p0);
        dec_cell1_k<<<dim3(8, 16, 1), 256>>>(dWih1, dWhh1, db1, p0 ^ 1, p1);
        fc1_k<<<dim3(8, 4), 256>>>(fc1W, fc1b, p1 ^ 1);
        fc2_k<<<kB / 8, 256>>>(fc2W, fc2b, tf, out, p);
        p0 ^= 1; p1 ^= 1;
    }
}

// round 6
// speedup vs baseline: 1.2356x; 1.2356x over previous
#include <cuda_runtime.h>
#include <cuda_fp16.h>
#include <cstdint>
#include <math.h>

constexpr int kB = 512, kS = 168, kI = 8, kH = 512, kF = 256, kP = 24, kG = 2048;
constexpr size_t kHS = (size_t)kB * kH;
constexpr int SMP = 72;              // padded smem row stride (halves)
constexpr int SBUF = 128 * SMP;      // halves per tile buffer

// ---------------- device scratch ----------------
__device__ __align__(256) float g_gates_big[(size_t)2 * kS * kB * kG]; // Gpre0 then G1
__device__ __align__(256) __half g_y0hi[(size_t)kS * kB * 2 * kH];
__device__ __align__(256) __half g_y0lo[(size_t)kS * kB * 2 * kH];
__device__ __align__(256) __half g_ehhi[8 * kHS], g_ehlo[8 * kHS];
__device__ __align__(256) float g_ehf[4 * kHS];
__device__ __align__(256) float g_ec[4 * kHS];
__device__ __align__(256) __half g_dhhi[4 * kHS], g_dhlo[4 * kHS];
__device__ __align__(256) float g_dc[2 * kHS];
__device__ __align__(256) float g_dh1f[kHS];
__device__ __align__(256) float g_dgates[(size_t)kB * kG];
__device__ __align__(256) float g_din[kB * kI];
__device__ __align__(256) float g_z[kB * kF];
__device__ __align__(256) float g_bint[3 * kG];

// fp16 hi/lo weight splits
__device__ __align__(256) __half g_Whh0h[2 * kG * kH], g_Whh0l[2 * kG * kH];
__device__ __align__(256) __half g_Whh1h[2 * kG * kH], g_Whh1l[2 * kG * kH];
__device__ __align__(256) __half g_Wih1h[(size_t)2 * kG * 2 * kH], g_Wih1l[(size_t)2 * kG * 2 * kH];
__device__ __align__(256) __half g_dWhh0h[kG * kH], g_dWhh0l[kG * kH];
__device__ __align__(256) __half g_dWih1h[kG * kH], g_dWih1l[kG * kH];
__device__ __align__(256) __half g_dWhh1h[kG * kH], g_dWhh1l[kG * kH];

// ---------------- PTX helpers ----------------
__device__ __forceinline__ uint32_t smem_u32(const void* p) {
    uint32_t a;
    asm("{ .reg .u64 t; cvta.to.shared.u64 t, %1; cvt.u32.u64 %0, t; }" : "=r"(a) : "l"(p));
    return a;
}
#define CP_ASYNC16(dst, src) \
    asm volatile("cp.async.cg.shared.global [%0], [%1], 16;" :: "r"(dst), "l"(src) : "memory")
#define CP_COMMIT() asm volatile("cp.async.commit_group;" ::: "memory")
#define CP_WAIT1() asm volatile("cp.async.wait_group 1;" ::: "memory")
#define CP_WAIT0() asm volatile("cp.async.wait_group 0;" ::: "memory")

#define MMA168(c, a, bb0, bb1) \
    asm volatile("mma.sync.aligned.m16n8k16.row.col.f32.f16.f16.f32 " \
        "{%0,%1,%2,%3}, {%4,%5,%6,%7}, {%8,%9}, {%0,%1,%2,%3};" \
        : "+f"((c)[0]), "+f"((c)[1]), "+f"((c)[2]), "+f"((c)[3]) \
        : "r"((a)[0]), "r"((a)[1]), "r"((a)[2]), "r"((a)[3]), "r"(bb0), "r"(bb1))

__device__ __forceinline__ float sigf(float x) { return __fdividef(1.f, 1.f + __expf(-x)); }

// column mapping: col j in [0,128): gate g=(j&1)+2*((j>>3)&1), unit_local=4*((j>>4)&7)+((j>>1)&3)
__device__ __forceinline__ int wrow_of_col(int j, int u0) {
    int g = (j & 1) + 2 * ((j >> 3) & 1);
    int ul = 4 * ((j >> 4) & 7) + ((j >> 1) & 3);
    return g * kH + u0 + ul;
}

// ---------------- unified MMA step / GEMM kernel ----------------
struct StepParams {
    const __half *Ahi, *Alo; long a_d;
    const __half *Bhi, *Blo; long b_d;
    const __half *A2hi, *A2lo; long a2_d;
    const __half *B2hi, *B2lo; long b2_d;
    int K1, K2, npairs;
    const float* gpre; long g_d, g_s; int g_r;
    float* c; long c_d;
    __half *Hhi, *Hlo; long h_d;
    float* Hf; long hf_d;
    __half *Yhi, *Ylo;
    float* Gout; long go_d;
    int mode, t, revz;
};

struct ChunkSrc { const __half* A; const __half* B; int k0; int K; };

__device__ __forceinline__ ChunkSrc chunk_src(const StepParams& P, int d, int ch) {
    int c1 = 3 * (P.K1 >> 6);
    int pr = (ch >= c1) ? 1 : 0;
    if (pr) ch -= c1;
    int K = pr ? P.K2 : P.K1;
    int per = K >> 6;
    int pass = ch / per;
    int k0 = (ch - pass * per) << 6;
    const __half* Ah = pr ? P.A2hi : P.Ahi;
    const __half* Al = pr ? P.A2lo : P.Alo;
    const __half* Bh = pr ? P.B2hi : P.Bhi;
    const __half* Bl = pr ? P.B2lo : P.Blo;
    long ad = pr ? P.a2_d : P.a_d, bd = pr ? P.b2_d : P.b_d;
    ChunkSrc r;
    r.A = ((pass == 1) ? Al : Ah) + (long)d * ad;
    r.B = ((pass == 2) ? Bl : Bh) + (long)d * bd;
    r.k0 = k0; r.K = K;
    return r;
}

__device__ __forceinline__ void prefetch_chunk(const ChunkSrc& cs, long mrow0, long wrow,
                                               int frow, int fcol, __half* bA, __half* bB) {
    const __half* ap = cs.A + (mrow0 + frow) * (long)cs.K + cs.k0 + fcol;
    const __half* bp = cs.B + wrow * (long)cs.K + cs.k0 + fcol;
    uint32_t da = smem_u32(bA + frow * SMP + fcol);
    uint32_t db = smem_u32(bB + frow * SMP + fcol);
#pragma unroll
    for (int i = 0; i < 4; ++i) {
        CP_ASYNC16(da + i * 16, ap + i * 8);
        CP_ASYNC16(db + i * 16, bp + i * 8);
    }
}

__device__ __forceinline__ void do_mma_chunk(const __half* bA, const __half* bB,
                                             int wm, int wn, int lane, float acc[2][8][4]) {
    const int lrow = lane & 15, lk = (lane >> 4) * 8;
#pragma unroll
    for (int kk = 0; kk < 4; ++kk) {
        uint32_t a[2][4];
#pragma unroll
        for (int mi = 0; mi < 2; ++mi) {
            uint32_t addr = smem_u32(bA + (wm * 32 + mi * 16 + lrow) * SMP + kk * 16 + lk);
            asm volatile("ldmatrix.sync.aligned.m8n8.x4.shared.b16 {%0,%1,%2,%3}, [%4];"
                : "=r"(a[mi][0]), "=r"(a[mi][1]), "=r"(a[mi][2]), "=r"(a[mi][3]) : "r"(addr));
        }
#pragma unroll
        for (int ni = 0; ni < 4; ++ni) {
            uint32_t b0, b1, b2, b3;
            uint32_t addr = smem_u32(bB + (wn * 64 + ni * 16 + lrow) * SMP + kk * 16 + lk);
            asm volatile("ldmatrix.sync.aligned.m8n8.x4.shared.b16 {%0,%1,%2,%3}, [%4];"
                : "=r"(b0), "=r"(b1), "=r"(b2), "=r"(b3) : "r"(addr));
#pragma unroll
            for (int mi = 0; mi < 2; ++mi) {
                MMA168(acc[mi][2 * ni], a[mi], b0, b2);
                MMA168(acc[mi][2 * ni + 1], a[mi], b1, b3);
            }
        }
    }
}

__global__ __launch_bounds__(256) void mma_step_k(StepParams P)
{
    extern __shared__ __half smp[];
    __half* bufA[2] = { smp, smp + 2 * SBUF };
    __half* bufB[2] = { smp + SBUF, smp + 3 * SBUF };
    const int tid = threadIdx.x, wid = tid >> 5, lane = tid & 31;
    const int wm = wid & 3, wn = wid >> 2;
    const int d = blockIdx.z;
    const int s = (P.revz && d) ? (kS - 1 - P.t) : P.t;
    const int u0 = blockIdx.y * 32;
    const long mrow0 = (long)blockIdx.x * 128;

    const int frow = tid >> 1, fcol = (tid & 1) * 32;
    const long wrow = wrow_of_col(frow, u0);

    float acc[2][8][4];
#pragma unroll
    for (int i = 0; i < 2; ++i)
#pragma unroll
        for (int j = 0; j < 8; ++j)
#pragma unroll
            for (int k = 0; k < 4; ++k) acc[i][j][k] = 0.f;

    const int NCH = 3 * (P.K1 >> 6) + ((P.npairs > 1) ? 3 * (P.K2 >> 6) : 0);

    prefetch_chunk(chunk_src(P, d, 0), mrow0, wrow, frow, fcol, bufA[0], bufB[0]);
    CP_COMMIT();
    for (int ch = 0; ch < NCH; ++ch) {
        if (ch + 1 < NCH) {
            prefetch_chunk(chunk_src(P, d, ch + 1), mrow0, wrow, frow, fcol,
                           bufA[(ch + 1) & 1], bufB[(ch + 1) & 1]);
            CP_COMMIT();
            CP_WAIT1();
        } else {
            CP_WAIT0();
        }
        __syncthreads();
        do_mma_chunk(bufA[ch & 1], bufB[ch & 1], wm, wn, lane, acc);
        __syncthreads();
    }

    // ---- epilogue ----
    const long r0row = mrow0 + wm * 32 + (lane >> 2);
    const int q = lane & 3;
    if (P.mode == 1) {
        const float* gp = P.gpre + (long)d * P.g_d;   // bias (g_r=0)
        float* go = P.Gout + (long)d * P.go_d;
#pragma unroll
        for (int mi = 0; mi < 2; ++mi)
#pragma unroll
            for (int s4 = 0; s4 < 4; ++s4) {
                int jb = (4 * wn + s4) * 16 + 2 * q;
                long Jb = 128L * blockIdx.y + jb;
#pragma unroll
                for (int rh = 0; rh < 2; ++rh) {
                    long row = r0row + mi * 16 + 8 * rh;
                    float2 v0 = { acc[mi][2 * s4][2 * rh] + gp[Jb],
                                  acc[mi][2 * s4][2 * rh + 1] + gp[Jb + 1] };
                    float2 v1 = { acc[mi][2 * s4 + 1][2 * rh] + gp[Jb + 8],
                                  acc[mi][2 * s4 + 1][2 * rh + 1] + gp[Jb + 9] };
                    *(float2*)&go[row * kG + Jb] = v0;
                    *(float2*)&go[row * kG + Jb + 8] = v1;
                }
            }
    } else {
#pragma unroll
        for (int mi = 0; mi < 2; ++mi)
#pragma unroll
            for (int s4 = 0; s4 < 4; ++s4) {
                int sg = 4 * wn + s4;
                int jb = sg * 16 + 2 * q;
                long Jb = 128L * blockIdx.y + jb;
                int unit = u0 + 4 * sg + q;
#pragma unroll
                for (int rh = 0; rh < 2; ++rh) {
                    long row = r0row + mi * 16 + 8 * rh;
                    float gi = acc[mi][2 * s4][2 * rh], gf = acc[mi][2 * s4][2 * rh + 1];
                    float gg = acc[mi][2 * s4 + 1][2 * rh], go_ = acc[mi][2 * s4 + 1][2 * rh + 1];
                    if (P.gpre) {
                        const float* gp = P.gpre + (long)d * P.g_d + (long)s * P.g_s
                                        + row * (long)P.g_r + Jb;
                        gi += gp[0]; gf += gp[1]; gg += gp[8]; go_ += gp[9];
                    }
                    gi = sigf(gi); gf = sigf(gf); gg = tanhf(gg); go_ = sigf(go_);
                    long ci = (long)d * P.c_d + row * kH + unit;
                    float cv = gf * P.c[ci] + gi * gg;
                    P.c[ci] = cv;
                    float hv = go_ * tanhf(cv);
                    __half hh = __float2half_rn(hv);
                    __half hl = __float2half_rn(hv - __half2float(hh));
                    long hidx = (long)d * P.h_d + row * kH + unit;
                    P.Hhi[hidx] = hh; P.Hlo[hidx] = hl;
                    if (P.Hf) P.Hf[(long)d * P.hf_d + row * kH + unit] = hv;
                    if (P.Yhi) {
                        long yi = ((long)s * kB + row) * (2 * kH) + (long)d * kH + unit;
                        P.Yhi[yi] = hh; P.Ylo[yi] = hl;
                    }
                }
            }
    }
}

// ---------------- support kernels ----------------
__global__ void zero_k()
{
    size_t i = (size_t)blockIdx.x * blockDim.x + threadIdx.x;
    size_t st = (size_t)gridDim.x * blockDim.x;
    for (size_t j = i; j < 8 * kHS; j += st) { g_ehhi[j] = __float2half(0.f); g_ehlo[j] = __float2half(0.f); }
    for (size_t j = i; j < 4 * kHS; j += st) g_ec[j] = 0.f;
}

__global__ void split_k(const float* __restrict__ src, __half* __restrict__ hi,
                        __half* __restrict__ lo, size_t n)
{
    size_t i = ((size_t)blockIdx.x * blockDim.x + threadIdx.x) * 4;
    size_t st = (size_t)gridDim.x * blockDim.x * 4;
    for (; i < n; i += st) {
        float4 v = *(const float4*)(src + i);
        float a[4] = {v.x, v.y, v.z, v.w};
#pragma unroll
        for (int k = 0; k < 4; ++k) {
            __half h = __float2half_rn(a[k]);
            hi[i + k] = h;
            lo[i + k] = __float2half_rn(a[k] - __half2float(h));
        }
    }
}

__global__ void inter_k(const float* __restrict__ src, float* __restrict__ dst, int nblk)
{
    int i = blockIdx.x * blockDim.x + threadIdx.x;
    if (i < nblk * kG) {
        int blk = i / kG, J = i % kG;
        int g = (J & 1) + 2 * ((J >> 3) & 1);
        int unit = 32 * (J >> 7) + 4 * ((J >> 4) & 7) + ((J >> 1) & 3);
        dst[blk * kG + J] = src[blk * kG + g * kH + unit];
    }
}

__global__ void gpre0_k(const float* __restrict__ x, const float* __restrict__ W, const float* __restrict__ b)
{
    __shared__ float xs[8];
    int sb = blockIdx.x;
    int s = sb / kB, bb = sb % kB;
    if (threadIdx.x < 8) xs[threadIdx.x] = x[((size_t)bb * kS + s) * kI + threadIdx.x];
    __syncthreads();
    float* out0 = g_gates_big + (size_t)sb * kG;
    for (int it = 0; it < 16; ++it) {
        int jf = it * 256 + threadIdx.x;
        int d = jf >> 11, J = jf & (kG - 1);
        int g = (J & 1) + 2 * ((J >> 3) & 1);
        int unit = 32 * (J >> 7) + 4 * ((J >> 4) & 7) + ((J >> 1) & 3);
        int w = g * kH + unit;
        const float* Wr = W + ((size_t)d * kG + w) * kI;
        float acc = b[d * kG + w];
#pragma unroll
        for (int k = 0; k < 8; ++k) acc += xs[k] * Wr[k];
        out0[(size_t)d * kS * kB * kG + J] = acc;
    }
}

__global__ void dxproj_k(const float* __restrict__ W, const float* __restrict__ b)
{
    __shared__ float xs[8];
    int bb = blockIdx.x;
    if (threadIdx.x < 8) xs[threadIdx.x] = g_din[bb * kI + threadIdx.x];
    __syncthreads();
    float* out = g_dgates + (size_t)bb * kG;
    for (int it = 0; it < 8; ++it) {
        int J = it * 256 + threadIdx.x;
        int g = (J & 1) + 2 * ((J >> 3) & 1);
        int unit = 32 * (J >> 7) + 4 * ((J >> 4) & 7) + ((J >> 1) & 3);
        int w = g * kH + unit;
        const float* Wr = W + (size_t)w * kI;
        float acc = b[w];
#pragma unroll
        for (int k = 0; k < 8; ++k) acc += xs[k] * Wr[k];
        out[J] = acc;
    }
}

__global__ void combine_k(const float* __restrict__ x)
{
    size_t i = (size_t)blockIdx.x * blockDim.x + threadIdx.x;
    if (i < kHS) {
        float v0 = g_ehf[i] + g_ehf[kHS + i];
        __half h0 = __float2half_rn(v0);
        g_dhhi[i] = h0; g_dhlo[i] = __float2half_rn(v0 - __half2float(h0));
        g_dc[i] = g_ec[i] + g_ec[kHS + i];
        float v1 = g_ehf[2 * kHS + i] + g_ehf[3 * kHS + i];
        __half h1 = __float2half_rn(v1);
        g_dhhi[2 * kHS + i] = h1; g_dhlo[2 * kHS + i] = __float2half_rn(v1 - __half2float(h1));
        g_dc[kHS + i] = g_ec[2 * kHS + i] + g_ec[3 * kHS + i];
    }
    if (i < kB * kI)
        g_din[i] = x[(i >> 3) * (size_t)(kS * kI) + (size_t)(kS - 1) * kI + (i & 7)];
}

__global__ __launch_bounds__(256) void fc1_k(const float* __restrict__ W, const float* __restrict__ b)
{
    __shared__ float Hs[16][64];
    __shared__ float Ws[64][17];
    int r0 = blockIdx.x * 64, j0 = blockIdx.y * 64;
    int tid = threadIdx.x;
    const float* h1 = g_dh1f + (size_t)r0 * kH;
    int j = tid & 63, rg = tid >> 6;
    float acc[16] = {};
    int lr = tid >> 2, lk = (tid & 3) * 4;
    for (int k0 = 0; k0 < kH; k0 += 16) {
        __syncthreads();
        {
            float4 v = *(const float4*)(h1 + (size_t)lr * kH + k0 + lk);
            Hs[lk][lr] = v.x; Hs[lk + 1][lr] = v.y; Hs[lk + 2][lr] = v.z; Hs[lk + 3][lr] = v.w;
        }
        {
            float4 v = *(const float4*)(W + (size_t)(j0 + lr) * kH + k0 + lk);
            Ws[lr][lk] = v.x; Ws[lr][lk + 1] = v.y; Ws[lr][lk + 2] = v.z; Ws[lr][lk + 3] = v.w;
        }
        __syncthreads();
#pragma unroll
        for (int kk = 0; kk < 16; ++kk) {
            float w = Ws[j][kk];
#pragma unroll
            for (int r = 0; r < 16; ++r) acc[r] += Hs[kk][rg * 16 + r] * w;
        }
    }
    float bb = b[j0 + j];
#pragma unroll
    for (int r = 0; r < 16; ++r) {
        float v = acc[r] + bb;
        g_z[(size_t)(r0 + rg * 16 + r) * kF + j0 + j] = v > 0.f ? v : 0.f;
    }
}

__global__ void fc2_k(const float* __restrict__ W2, const float* __restrict__ b2,
                      const float* __restrict__ tf, float* __restrict__ out, int p)
{
    int w = threadIdx.x >> 5, lane = threadIdx.x & 31;
    int row = blockIdx.x * 8 + w;
    const float* z = g_z + (size_t)row * kF;
    float s = 0.f;
    for (int k = lane; k < kF; k += 32) s += z[k] * W2[k];
#pragma unroll
    for (int o = 16; o; o >>= 1) s += __shfl_xor_sync(0xffffffffu, s, o);
    if (lane == 0) {
        float pred = s + b2[0];
        out[row * kP + p] = pred;
        g_din[row * kI] = pred;
    }
    if (lane >= 1 && lane < 8)
        g_din[row * kI + lane] = tf[(size_t)row * (kP * kI) + (size_t)p * kI + lane];
}

// ---------------- host driver ----------------
static void* dptr(const void* sym) { void* p = nullptr; cudaGetSymbolAddress(&p, sym); return p; }

extern "C" void kernel_launch(void* const* d_in, const int* in_sizes, int n_in,
                              void* d_out, int out_size)
{
    (void)in_sizes; (void)n_in; (void)out_size;
    const float* x     = (const float*)d_in[0];
    const float* tf    = (const float*)d_in[1];
    const float* eWih0 = (const float*)d_in[2];
    const float* eWhh0 = (const float*)d_in[3];
    const float* eb0   = (const float*)d_in[4];
    const float* eWih1 = (const float*)d_in[5];
    const float* eWhh1 = (const float*)d_in[6];
    const float* eb1   = (const float*)d_in[7];
    const float* dWih0 = (const float*)d_in[8];
    const float* dWhh0 = (const float*)d_in[9];
    const float* db0   = (const float*)d_in[10];
    const float* dWih1 = (const float*)d_in[11];
    const float* dWhh1 = (const float*)d_in[12];
    const float* db1   = (const float*)d_in[13];
    const float* fc1W  = (const float*)d_in[14];
    const float* fc1b  = (const float*)d_in[15];
    const float* fc2W  = (const float*)d_in[16];
    const float* fc2b  = (const float*)d_in[17];
    float* out = (float*)d_out;

    static bool init_done = false;
    static __half *Whh0h, *Whh0l, *Whh1h, *Whh1l, *Wih1h, *Wih1l;
    static __half *dWhh0h, *dWhh0l, *dWih1h, *dWih1l, *dWhh1h, *dWhh1l;
    static __half *ehhi, *ehlo, *dhhi, *dhlo, *y0hi, *y0lo;
    static float *gbig, *ec, *ehf, *dc, *dh1f, *dgates, *bint;
    const int SMEM = 4 * SBUF * (int)sizeof(__half);
    if (!init_done) {
        Whh0h = (__half*)dptr(g_Whh0h); Whh0l = (__half*)dptr(g_Whh0l);
        Whh1h = (__half*)dptr(g_Whh1h); Whh1l = (__half*)dptr(g_Whh1l);
        Wih1h = (__half*)dptr(g_Wih1h); Wih1l = (__half*)dptr(g_Wih1l);
        dWhh0h = (__half*)dptr(g_dWhh0h); dWhh0l = (__half*)dptr(g_dWhh0l);
        dWih1h = (__half*)dptr(g_dWih1h); dWih1l = (__half*)dptr(g_dWih1l);
        dWhh1h = (__half*)dptr(g_dWhh1h); dWhh1l = (__half*)dptr(g_dWhh1l);
        ehhi = (__half*)dptr(g_ehhi); ehlo = (__half*)dptr(g_ehlo);
        dhhi = (__half*)dptr(g_dhhi); dhlo = (__half*)dptr(g_dhlo);
        y0hi = (__half*)dptr(g_y0hi); y0lo = (__half*)dptr(g_y0lo);
        gbig = (float*)dptr(g_gates_big); ec = (float*)dptr(g_ec); ehf = (float*)dptr(g_ehf);
        dc = (float*)dptr(g_dc); dh1f = (float*)dptr(g_dh1f);
        dgates = (float*)dptr(g_dgates); bint = (float*)dptr(g_bint);
        cudaFuncSetAttribute(mma_step_k, cudaFuncAttributeMaxDynamicSharedMemorySize, SMEM);
        init_done = true;
    }

    zero_k<<<2048, 256>>>();
    split_k<<<512, 256>>>(eWhh0, Whh0h, Whh0l, (size_t)2 * kG * kH);
    split_k<<<512, 256>>>(eWhh1, Whh1h, Whh1l, (size_t)2 * kG * kH);
    split_k<<<1024, 256>>>(eWih1, Wih1h, Wih1l, (size_t)2 * kG * 2 * kH);
    split_k<<<256, 256>>>(dWhh0, dWhh0h, dWhh0l, (size_t)kG * kH);
    split_k<<<256, 256>>>(dWih1, dWih1h, dWih1l, (size_t)kG * kH);
    split_k<<<256, 256>>>(dWhh1, dWhh1h, dWhh1l, (size_t)kG * kH);
    inter_k<<<(2 * kG + 255) / 256, 256>>>(eb1, bint, 2);
    inter_k<<<(kG + 255) / 256, 256>>>(db1, bint + 2 * kG, 1);
    gpre0_k<<<kS * kB, 256>>>(x, eWih0, eb0);

    const long SDG = (long)kS * kB * kG;
    StepParams P;

    // ---- encoder layer 0 ----
    for (int t = 0; t < kS; ++t) {
        int ping = t & 1;
        P = {};
        P.Ahi = ehhi + ping * kHS; P.Alo = ehlo + ping * kHS; P.a_d = 2 * (long)kHS;
        P.Bhi = Whh0h; P.Blo = Whh0l; P.b_d = (long)kG * kH;
        P.K1 = kH; P.npairs = 1;
        P.gpre = gbig; P.g_d = SDG; P.g_s = (long)kB * kG; P.g_r = kG;
        P.c = ec; P.c_d = kHS;
        P.Hhi = ehhi + (ping ^ 1) * kHS; P.Hlo = ehlo + (ping ^ 1) * kHS; P.h_d = 2 * (long)kHS;
        P.Hf = ehf; P.hf_d = kHS;
        P.Yhi = y0hi; P.Ylo = y0lo;
        P.mode = 0; P.t = t; P.revz = 1;
        mma_step_k<<<dim3(4, 16, 2), 256, SMEM>>>(P);
    }

    // ---- big L1 input projection ----
    P = {};
    P.Ahi = y0hi; P.Alo = y0lo; P.a_d = 0;
    P.Bhi = Wih1h; P.Blo = Wih1l; P.b_d = (long)kG * 2 * kH;
    P.K1 = 2 * kH; P.npairs = 1;
    P.gpre = bint; P.g_d = kG; P.g_s = 0; P.g_r = 0;
    P.Gout = gbig; P.go_d = SDG;
    P.mode = 1; P.t = 0; P.revz = 0;
    mma_step_k<<<dim3(672, 16, 2), 256, SMEM>>>(P);

    // ---- encoder layer 1 ----
    for (int t = 0; t < kS; ++t) {
        int ping = t & 1;
        P = {};
        P.Ahi = ehhi + (4 + ping) * kHS; P.Alo = ehlo + (4 + ping) * kHS; P.a_d = 2 * (long)kHS;
        P.Bhi = Whh1h; P.Blo = Whh1l; P.b_d = (long)kG * kH;
        P.K1 = kH; P.npairs = 1;
        P.gpre = gbig; P.g_d = SDG; P.g_s = (long)kB * kG; P.g_r = kG;
        P.c = ec + 2 * kHS; P.c_d = kHS;
        P.Hhi = ehhi + (4 + (ping ^ 1)) * kHS; P.Hlo = ehlo + (4 + (ping ^ 1)) * kHS; P.h_d = 2 * (long)kHS;
        P.Hf = ehf + 2 * kHS; P.hf_d = kHS;
        P.mode = 0; P.t = t; P.revz = 1;
        mma_step_k<<<dim3(4, 16, 2), 256, SMEM>>>(P);
    }

    combine_k<<<1024, 256>>>(x);

    // ---- decoder ----
    int p0 = 0, p1 = 0;
    for (int p = 0; p < kP; ++p) {
        dxproj_k<<<kB, 256>>>(dWih0, db0);

        P = {};
        P.Ahi = dhhi + p0 * kHS; P.Alo = dhlo + p0 * kHS;
        P.Bhi = dWhh0h; P.Blo = dWhh0l;
        P.K1 = kH; P.npairs = 1;
        P.gpre = dgates; P.g_r = kG;
        P.c = dc;
        P.Hhi = dhhi + (p0 ^ 1) * kHS; P.Hlo = dhlo + (p0 ^ 1) * kHS;
        P.mode = 0;
        mma_step_k<<<dim3(4, 16, 1), 256, SMEM>>>(P);

        P = {};
        P.Ahi = dhhi + (2 + p1) * kHS; P.Alo = dhlo + (2 + p1) * kHS;
        P.Bhi = dWhh1h; P.Blo = dWhh1l;
        P.A2hi = dhhi + (p0 ^ 1) * kHS; P.A2lo = dhlo + (p0 ^ 1) * kHS;
        P.B2hi = dWih1h; P.B2lo = dWih1l;
        P.K1 = kH; P.K2 = kH; P.npairs = 2;
        P.gpre = bint + 2 * kG; P.g_r = 0;
        P.c = dc + kHS;
        P.Hhi = dhhi + (2 + (p1 ^ 1)) * kHS; P.Hlo = dhlo + (2 + (p1 ^ 1)) * kHS;
        P.Hf = dh1f;
        P.mode = 0;
        mma_step_k<<<dim3(4, 16, 1), 256, SMEM>>>(P);

        fc1_k<<<dim3(8, 4), 256>>>(fc1W, fc1b);
        fc2_k<<<kB / 8, 256>>>(fc2W, fc2b, tf, out, p);
        p0 ^= 1; p1 ^= 1;
    }
}